// round 11
// baseline (speedup 1.0000x reference)
#include <cuda_runtime.h>
#include <cuda_bf16.h>
#include <cstdint>
#include <math.h>

// ---------------- problem constants ----------------
#define BB   4096
#define DD   256
#define HH   512
#define KK   10
#define HEADN 94
#define LL   4
#define SS   10
#define NLG  (DD * 10)     // 2560 logit cols
#define NMS  (DD * 20)     // 5120 mean/scale cols

typedef unsigned long long ull;

// ---------------- scratch ----------------
__device__ float g_H[BB * HH];
__device__ float g_T[BB * HH];
__device__ float g_WLG[HH * NLG];
__device__ float g_BLG[NLG];
__device__ float g_LG[(size_t)BB * NLG];
__device__ __nv_bfloat16 g_Hh[BB * HH];
__device__ __nv_bfloat16 g_Hl[BB * HH];
__device__ __nv_bfloat16 g_WBTh[NMS * HH];
__device__ __nv_bfloat16 g_WBTl[NMS * HH];
__device__ float g_BMS[NMS];
__device__ float g_MS[(size_t)BB * NMS];

// ---------------- f32x2 helpers ----------------
__device__ __forceinline__ ull pack2(float lo, float hi) {
    ull r; asm("mov.b64 %0, {%1, %2};" : "=l"(r) : "f"(lo), "f"(hi)); return r;
}
__device__ __forceinline__ ull fma2(ull a, ull b, ull c) {
    ull r; asm("fma.rn.f32x2 %0, %1, %2, %3;" : "=l"(r) : "l"(a), "l"(b), "l"(c)); return r;
}
__device__ __forceinline__ void unpack2(ull v, float& lo, float& hi) {
    asm("mov.b64 {%0, %1}, %2;" : "=f"(lo), "=f"(hi) : "l"(v));
}

// ---------------- cp.async ----------------
__device__ __forceinline__ void cp_async16(uint32_t dst, const void* src) {
    asm volatile("cp.async.cg.shared.global [%0], [%1], 16;" :: "r"(dst), "l"(src));
}
__device__ __forceinline__ void cp_commit() { asm volatile("cp.async.commit_group;"); }
__device__ __forceinline__ void cp_wait0()  { asm volatile("cp.async.wait_group 0;"); }
__device__ __forceinline__ void cp_wait1()  { asm volatile("cp.async.wait_group 1;"); }

// ---------------- mma / ldmatrix ----------------
__device__ __forceinline__ void ldsm4(uint32_t* r, uint32_t addr) {
    asm volatile("ldmatrix.sync.aligned.m8n8.x4.shared.b16 {%0,%1,%2,%3}, [%4];"
                 : "=r"(r[0]), "=r"(r[1]), "=r"(r[2]), "=r"(r[3]) : "r"(addr));
}
__device__ __forceinline__ void mma_bf16(float* c, const uint32_t* a, uint32_t b0, uint32_t b1) {
    asm volatile("mma.sync.aligned.m16n8k16.row.col.f32.bf16.bf16.f32 "
                 "{%0,%1,%2,%3}, {%4,%5,%6,%7}, {%8,%9}, {%0,%1,%2,%3};"
                 : "+f"(c[0]), "+f"(c[1]), "+f"(c[2]), "+f"(c[3])
                 : "r"(a[0]), "r"(a[1]), "r"(a[2]), "r"(a[3]), "r"(b0), "r"(b1));
}

// ---------------- threefry2x32 (bit-exact JAX) ----------------
__host__ __device__ __forceinline__ uint32_t rotl32(uint32_t x, int r) {
#if defined(__CUDA_ARCH__)
    return __funnelshift_l(x, x, r);
#else
    return (x << r) | (x >> (32 - r));
#endif
}

__host__ __device__ __forceinline__ void threefry2x32(
    uint32_t k0, uint32_t k1, uint32_t x0, uint32_t x1,
    uint32_t& o0, uint32_t& o1)
{
    uint32_t k2 = k0 ^ k1 ^ 0x1BD11BDAu;
    x0 += k0; x1 += k1;
    x0 += x1; x1 = rotl32(x1, 13); x1 ^= x0;
    x0 += x1; x1 = rotl32(x1, 15); x1 ^= x0;
    x0 += x1; x1 = rotl32(x1, 26); x1 ^= x0;
    x0 += x1; x1 = rotl32(x1, 6);  x1 ^= x0;
    x0 += k1; x1 += k2 + 1u;
    x0 += x1; x1 = rotl32(x1, 17); x1 ^= x0;
    x0 += x1; x1 = rotl32(x1, 29); x1 ^= x0;
    x0 += x1; x1 = rotl32(x1, 16); x1 ^= x0;
    x0 += x1; x1 = rotl32(x1, 24); x1 ^= x0;
    x0 += k2; x1 += k0 + 2u;
    x0 += x1; x1 = rotl32(x1, 13); x1 ^= x0;
    x0 += x1; x1 = rotl32(x1, 15); x1 ^= x0;
    x0 += x1; x1 = rotl32(x1, 26); x1 ^= x0;
    x0 += x1; x1 = rotl32(x1, 6);  x1 ^= x0;
    x0 += k0; x1 += k1 + 3u;
    x0 += x1; x1 = rotl32(x1, 17); x1 ^= x0;
    x0 += x1; x1 = rotl32(x1, 29); x1 ^= x0;
    x0 += x1; x1 = rotl32(x1, 16); x1 ^= x0;
    x0 += x1; x1 = rotl32(x1, 24); x1 ^= x0;
    x0 += k1; x1 += k2 + 4u;
    x0 += x1; x1 = rotl32(x1, 13); x1 ^= x0;
    x0 += x1; x1 = rotl32(x1, 15); x1 ^= x0;
    x0 += x1; x1 = rotl32(x1, 26); x1 ^= x0;
    x0 += x1; x1 = rotl32(x1, 6);  x1 ^= x0;
    x0 += k2; x1 += k0 + 5u;
    o0 = x0; o1 = x1;
}

__device__ __forceinline__ uint32_t tf_bits(uint32_t k0, uint32_t k1, uint32_t idx) {
    uint32_t o0, o1;
    threefry2x32(k0, k1, 0u, idx, o0, o1);
    return o0 ^ o1;
}

// ---------------- XLA-exact erfinv ----------------
__device__ __forceinline__ float erfinv_xla(float x) {
    float w = -logf((1.0f - x) * (1.0f + x));
    float p;
    if (w < 5.0f) {
        w -= 2.5f;
        p = 2.81022636e-08f;
        p = fmaf(p, w, 3.43273939e-07f);
        p = fmaf(p, w, -3.5233877e-06f);
        p = fmaf(p, w, -4.39150654e-06f);
        p = fmaf(p, w, 0.00021858087f);
        p = fmaf(p, w, -0.00125372503f);
        p = fmaf(p, w, -0.00417768164f);
        p = fmaf(p, w, 0.246640727f);
        p = fmaf(p, w, 1.50140941f);
    } else {
        w = sqrtf(w) - 3.0f;
        p = -0.000200214257f;
        p = fmaf(p, w, 0.000100950558f);
        p = fmaf(p, w, 0.00134934322f);
        p = fmaf(p, w, -0.00367342844f);
        p = fmaf(p, w, 0.00573950773f);
        p = fmaf(p, w, -0.0076224613f);
        p = fmaf(p, w, 0.00943887047f);
        p = fmaf(p, w, 1.00167406f);
        p = fmaf(p, w, 2.83297682f);
    }
    return p * x;
}

__device__ __forceinline__ float bits_to_unit(uint32_t b) {
    return __uint_as_float((b >> 9) | 0x3F800000u) - 1.0f;
}

// ---------------- gather kernels ----------------
__global__ void gather_lg(const float* __restrict__ Wf, const float* __restrict__ bf) {
    int t = blockIdx.x * blockDim.x + threadIdx.x;
    const int total = HH * NLG;
    if (t < total) {
        int n = t % NLG;
        int k = t / NLG;
        int d = n / 10, j = n - d * 10;
        g_WLG[t] = Wf[(size_t)k * (DD * HEADN) + d * HEADN + j];
    } else if (t < total + NLG) {
        int n = t - total;
        int d = n / 10, j = n - d * 10;
        g_BLG[n] = bf[d * HEADN + j];
    }
}

__global__ void gather_ms_t(const float* __restrict__ Wf) {
    __shared__ float tile[32][33];
    int n0 = blockIdx.x * 32;
    int k0 = blockIdx.y * 32;
    int tx = threadIdx.x & 31;
    int ty = threadIdx.x >> 5;
#pragma unroll
    for (int i = 0; i < 4; i++) {
        int k = k0 + ty + i * 8;
        int n = n0 + tx;
        int d = n / 20, r = n - d * 20;
        tile[ty + i * 8][tx] = Wf[(size_t)k * (DD * HEADN) + d * HEADN + 10 + r];
    }
    __syncthreads();
#pragma unroll
    for (int i = 0; i < 4; i++) {
        int n = n0 + ty + i * 8;
        int k = k0 + tx;
        float w = tile[tx][ty + i * 8];
        __nv_bfloat16 wh = __float2bfloat16(w);
        g_WBTh[(size_t)n * HH + k] = wh;
        g_WBTl[(size_t)n * HH + k] = __float2bfloat16(w - __bfloat162float(wh));
    }
}

__global__ void gather_bms(const float* __restrict__ bf) {
    int n = blockIdx.x * blockDim.x + threadIdx.x;
    if (n >= NMS) return;
    int d = n / 20, r = n - d * 20;
    g_BMS[n] = bf[d * HEADN + 10 + r];
}

// ---------------- exact fp32 SGEMM v3 (64x128 tile, 256 thr, 4x8 microtile) ----
// Per-element k-accumulation order and fma2 lane pairing identical to prior
// versions -> bit-identical outputs.
template <bool RELU_A, bool ADD_C, bool PREP, bool BF16OUT>
__global__ __launch_bounds__(256, 2) void sgemm_f32x2(
    const float* __restrict__ A, const float* __restrict__ Xm,
    const float* __restrict__ Bm,
    const float* __restrict__ bias, float* __restrict__ C,
    int N, int Kd)
{
    __shared__ float As[2][16][68];
    __shared__ float Bs[2][16][128];

    const int t  = threadIdx.x;
    const int bm = blockIdx.y * 64;
    const int bn = blockIdx.x * 128;
    const int tx = t & 15;
    const int tyy = t >> 4;           // 0..15
    const int rowbase = tyy * 4;

    // A fill: 1 float4 per thread
    const int arow = t >> 2;          // 0..63
    const int ak   = (t & 3) * 4;     // 0,4,8,12
    // B fill: 2 float4 per thread
    const int brow = t >> 4;          // 0..15
    const int bcol = (t & 15) * 8;

    ull acc2[4][4];
#pragma unroll
    for (int i = 0; i < 4; i++)
#pragma unroll
        for (int j = 0; j < 4; j++) acc2[i][j] = 0ull;

    float4 aR, bR0, bR1;

    auto loadG = [&](int k0) {
        if (PREP) {
            int col0 = k0 + ak;
            const float* xrow = A  + (size_t)(bm + arow) * DD;
            const float* mrow = Xm + (size_t)(bm + arow) * DD;
            if (col0 < DD) {
                float4 xv = *reinterpret_cast<const float4*>(xrow + col0);
                float4 mv = *reinterpret_cast<const float4*>(mrow + col0);
                aR = make_float4(xv.x * mv.x, xv.y * mv.y, xv.z * mv.z, xv.w * mv.w);
            } else {
                aR = *reinterpret_cast<const float4*>(mrow + col0 - DD);
            }
        } else {
            aR = *reinterpret_cast<const float4*>(A + (size_t)(bm + arow) * Kd + k0 + ak);
            if (RELU_A) {
                aR.x = fmaxf(aR.x, 0.f); aR.y = fmaxf(aR.y, 0.f);
                aR.z = fmaxf(aR.z, 0.f); aR.w = fmaxf(aR.w, 0.f);
            }
        }
        const float* Bp = Bm + (size_t)(k0 + brow) * N + bn + bcol;
        bR0 = *reinterpret_cast<const float4*>(Bp);
        bR1 = *reinterpret_cast<const float4*>(Bp + 4);
    };
    auto storeS = [&](int p) {
        As[p][ak + 0][arow] = aR.x;
        As[p][ak + 1][arow] = aR.y;
        As[p][ak + 2][arow] = aR.z;
        As[p][ak + 3][arow] = aR.w;
        *reinterpret_cast<float4*>(&Bs[p][brow][bcol])     = bR0;
        *reinterpret_cast<float4*>(&Bs[p][brow][bcol + 4]) = bR1;
    };

    loadG(0);
    storeS(0);
    __syncthreads();

    const int T = Kd >> 4;
    int p = 0;
#pragma unroll 1
    for (int tk = 0; tk < T; tk++) {
        if (tk + 1 < T) loadG((tk + 1) << 4);
#pragma unroll
        for (int kk = 0; kk < 16; kk++) {
            float a[4];
            *reinterpret_cast<float4*>(a) =
                *reinterpret_cast<const float4*>(&As[p][kk][rowbase]);
            ulonglong2 bq0 = *reinterpret_cast<const ulonglong2*>(&Bs[p][kk][tx * 8]);
            ulonglong2 bq1 = *reinterpret_cast<const ulonglong2*>(&Bs[p][kk][tx * 8 + 4]);
#pragma unroll
            for (int i = 0; i < 4; i++) {
                ull a2 = pack2(a[i], a[i]);
                acc2[i][0] = fma2(a2, bq0.x, acc2[i][0]);
                acc2[i][1] = fma2(a2, bq0.y, acc2[i][1]);
                acc2[i][2] = fma2(a2, bq1.x, acc2[i][2]);
                acc2[i][3] = fma2(a2, bq1.y, acc2[i][3]);
            }
        }
        if (tk + 1 < T) {
            storeS(p ^ 1);
            __syncthreads();
            p ^= 1;
        }
    }

    float4 bia0 = *reinterpret_cast<const float4*>(bias + bn + tx * 8);
    float4 bia1 = *reinterpret_cast<const float4*>(bias + bn + tx * 8 + 4);
#pragma unroll
    for (int i = 0; i < 4; i++) {
        size_t roff = (size_t)(bm + rowbase + i) * N + bn + tx * 8;
        float* crow = C + roff;
        float v[8];
        unpack2(acc2[i][0], v[0], v[1]);
        unpack2(acc2[i][1], v[2], v[3]);
        unpack2(acc2[i][2], v[4], v[5]);
        unpack2(acc2[i][3], v[6], v[7]);
        float4 r0, r1;
        r0.x = v[0] + bia0.x; r0.y = v[1] + bia0.y;
        r0.z = v[2] + bia0.z; r0.w = v[3] + bia0.w;
        r1.x = v[4] + bia1.x; r1.y = v[5] + bia1.y;
        r1.z = v[6] + bia1.z; r1.w = v[7] + bia1.w;
        if (ADD_C) {
            float4 c0 = *reinterpret_cast<const float4*>(crow);
            float4 c1 = *reinterpret_cast<const float4*>(crow + 4);
            r0.x += c0.x; r0.y += c0.y; r0.z += c0.z; r0.w += c0.w;
            r1.x += c1.x; r1.y += c1.y; r1.z += c1.z; r1.w += c1.w;
        }
        *reinterpret_cast<float4*>(crow)     = r0;
        *reinterpret_cast<float4*>(crow + 4) = r1;
        if (BF16OUT) {
            float rv[8] = {r0.x, r0.y, r0.z, r0.w, r1.x, r1.y, r1.z, r1.w};
            __nv_bfloat16 hh[8], hl[8];
#pragma unroll
            for (int m = 0; m < 8; m++) {
                hh[m] = __float2bfloat16(rv[m]);
                hl[m] = __float2bfloat16(rv[m] - __bfloat162float(hh[m]));
            }
            *reinterpret_cast<uint4*>(g_Hh + roff) = *reinterpret_cast<uint4*>(hh);
            *reinterpret_cast<uint4*>(g_Hl + roff) = *reinterpret_cast<uint4*>(hl);
        }
    }
}

// ---------------- bf16-split HMMA GEMM v2 ----------------
__global__ __launch_bounds__(256, 2) void musc_mma2() {
    extern __shared__ char smc[];
    const uint32_t smbase = (uint32_t)__cvta_generic_to_shared(smc);

    const int t = threadIdx.x;
    const int w = t >> 5;
    const int l = t & 31;
    const int wm = w & 3;
    const int wn = w >> 2;
    const int bn = blockIdx.x * 128;
    const int bm = blockIdx.y * 128;

    const int tile = t >> 6;
    const int sub  = t & 63;
    const __nv_bfloat16* gsrc =
        (tile == 0) ? g_Hh : (tile == 1) ? g_Hl : (tile == 2) ? g_WBTh : g_WBTl;
    const int gbase = (tile < 2) ? bm : bn;

    auto issue = [&](int k0, int p) {
        uint32_t dbase = smbase + (uint32_t)(p * 40960 + tile * 10240);
#pragma unroll
        for (int rr = 0; rr < 2; rr++) {
            int row = sub * 2 + rr;
            const __nv_bfloat16* s = gsrc + (size_t)(gbase + row) * HH + k0;
            uint32_t dst = dbase + (uint32_t)(row * 80);
            cp_async16(dst,      s);
            cp_async16(dst + 16, reinterpret_cast<const char*>(s) + 16);
            cp_async16(dst + 32, reinterpret_cast<const char*>(s) + 32);
            cp_async16(dst + 48, reinterpret_cast<const char*>(s) + 48);
        }
    };

    const uint32_t a_off0 = (uint32_t)((wm * 32 +      (l & 15)) * 80 + ((l >> 4) << 4));
    const uint32_t a_off1 = (uint32_t)((wm * 32 + 16 + (l & 15)) * 80 + ((l >> 4) << 4));
    const uint32_t b_row  = (uint32_t)((l & 7) + ((l >> 4) & 1) * 8);
    const uint32_t b_koff = (uint32_t)(((l >> 3) & 1) << 4);

    float acc[2][8][4];
#pragma unroll
    for (int f = 0; f < 2; f++)
#pragma unroll
        for (int i = 0; i < 8; i++)
#pragma unroll
            for (int j = 0; j < 4; j++) acc[f][i][j] = 0.0f;

    issue(0, 0);
    cp_commit();

    const int T = HH / 32;
    int p = 0;
#pragma unroll 1
    for (int tk = 0; tk < T; tk++) {
        if (tk + 1 < T) {
            issue((tk + 1) * 32, p ^ 1);
            cp_commit();
            cp_wait1();
        } else {
            cp_wait0();
        }
        __syncthreads();

        uint32_t base = smbase + (uint32_t)(p * 40960);
#pragma unroll
        for (int ks = 0; ks < 2; ks++) {
            uint32_t ksb = (uint32_t)(ks * 32);
            uint32_t ah[2][4], al[2][4];
            ldsm4(ah[0], base + a_off0 + ksb);
            ldsm4(ah[1], base + a_off1 + ksb);
            ldsm4(al[0], base + 10240 + a_off0 + ksb);
            ldsm4(al[1], base + 10240 + a_off1 + ksb);
#pragma unroll
            for (int q = 0; q < 4; q++) {
                uint32_t boff = (uint32_t)((wn * 64 + q * 16 + b_row) * 80) + b_koff + ksb;
                uint32_t bh[4], bl[4];
                ldsm4(bh, base + 20480 + boff);
                ldsm4(bl, base + 30720 + boff);
#pragma unroll
                for (int f = 0; f < 2; f++) {
#pragma unroll
                    for (int h = 0; h < 2; h++) {
                        float* a = acc[f][2 * q + h];
                        mma_bf16(a, ah[f], bh[2 * h], bh[2 * h + 1]);
                        mma_bf16(a, ah[f], bl[2 * h], bl[2 * h + 1]);
                        mma_bf16(a, al[f], bh[2 * h], bh[2 * h + 1]);
                    }
                }
            }
        }
        __syncthreads();
        p ^= 1;
    }

    const int g  = l >> 2;
    const int tt = l & 3;
#pragma unroll
    for (int f = 0; f < 2; f++) {
        int m0 = bm + wm * 32 + f * 16 + g;
#pragma unroll
        for (int nb = 0; nb < 8; nb++) {
            int n = bn + wn * 64 + nb * 8 + tt * 2;
            float2 bia = *reinterpret_cast<const float2*>(g_BMS + n);
            float2 v0 = make_float2(acc[f][nb][0] + bia.x, acc[f][nb][1] + bia.y);
            float2 v1 = make_float2(acc[f][nb][2] + bia.x, acc[f][nb][3] + bia.y);
            *reinterpret_cast<float2*>(g_MS + (size_t)m0 * NMS + n)       = v0;
            *reinterpret_cast<float2*>(g_MS + (size_t)(m0 + 8) * NMS + n) = v1;
        }
    }
}

// ---------------- fused tail (exponential-race argmax + exact fallback) ----
__global__ void fused_tail(const float* __restrict__ x, const float* __restrict__ mask,
                           float* __restrict__ out,
                           uint32_t kc0, uint32_t kc1, uint32_t kn0, uint32_t kn1)
{
    int t = blockIdx.x * blockDim.x + threadIdx.x;
    if (t >= BB * DD) return;
    int b = t >> 8;
    int d = t & (DD - 1);

    const float* lrow = g_LG + (size_t)b * NLG + d * 10;
    const float* mrow = g_MS + (size_t)b * NMS + d * 20;
    float lg[KK], mu[KK], sc[KK];
#pragma unroll
    for (int j = 0; j < KK; j++) lg[j] = lrow[j];
#pragma unroll
    for (int j = 0; j < KK; j++) mu[j] = mrow[j];
#pragma unroll
    for (int j = 0; j < KK; j++) {
        float v = mrow[10 + j];
        sc[j] = fmaxf(v, 0.0f) + log1pf(expf(-fabsf(v))) + 0.001f;
    }
    float q  = 1.0f - mask[t];
    float xu = x[t] * q;

    float mx = lg[0];
#pragma unroll
    for (int j = 1; j < KK; j++) mx = fmaxf(mx, lg[j]);
    float se = 0.0f;
#pragma unroll
    for (int j = 0; j < KK; j++) se += expf(lg[j] - mx);
    float lse = logf(se);

    float term[KK];
    float m2v = -1e30f;
#pragma unroll
    for (int j = 0; j < KK; j++) {
        float z   = (xu - mu[j]) / sc[j];
        float cll = -0.5f * z * z - logf(sc[j]) - 0.9189385332046727f;
        term[j] = (lg[j] - mx - lse) + cll;
        m2v = fmaxf(m2v, term[j]);
    }
    float s2 = 0.0f;
#pragma unroll
    for (int j = 0; j < KK; j++) s2 += expf(term[j] - m2v);
    out[t] = (m2v + logf(s2)) * q;

    float pm = 0.0f;
#pragma unroll
    for (int j = 0; j < KK; j++) pm += (expf(lg[j] - mx) / se) * mu[j];
    out[BB * DD + SS * BB * DD + t] = pm * q;

    // surrogate weights (per-j, reused for all 10 samples)
    float E[KK];
#pragma unroll
    for (int j = 0; j < KK; j++) E[j] = __expf(-lg[j]);

    float* smp = out + BB * DD;
    const float TINY = 1.17549435e-38f;

#pragma unroll 1
    for (int s = 0; s < SS; s++) {
        uint32_t idx_e = (uint32_t)(s * BB + b) * DD + (uint32_t)d;
        uint32_t base  = idx_e * KK;
        float e[KK];
        float m1 = 3.4e38f, m2 = 3.4e38f;
        int a = 0;
#pragma unroll
        for (int j = 0; j < KK; j++) {
            uint32_t bits = tf_bits(kc0, kc1, base + j);
            float f = bits_to_unit(bits);
            float u = fmaxf(TINY, f + TINY);
            e[j] = -logf(u);                 // exponential variate (bit-exact piece)
            float mm = e[j] * E[j];          // surrogate race value
            if (mm < m1) { m2 = m1; m1 = mm; a = j; }
            else if (mm < m2) { m2 = mm; }
        }
        // guard: if runner-up within 1e-3 relative, recompute exact argmax
        if (!(m2 > fmaf(m1, 1e-3f, m1))) {
            float best = -1e30f;
            a = 0;
#pragma unroll
            for (int j = 0; j < KK; j++) {
                float g = -logf(e[j]);       // exact gumbel (same bits as R8)
                float v = lg[j] + g;
                if (v > best) { best = v; a = j; }
            }
        }
        float mua = 0.f, sca = 0.f;
#pragma unroll
        for (int j = 0; j < KK; j++) {
            if (a == j) { mua = mu[j]; sca = sc[j]; }
        }
        uint32_t ebits = tf_bits(kn0, kn1, idx_e);
        const float LO = -0.99999994f;
        float u = fmaxf(LO, fmaf(bits_to_unit(ebits), 2.0f, LO));
        float eps = 1.41421356237309515f * erfinv_xla(u);
        smp[(b * SS + s) * DD + d] = (mua + sca * eps) * q;
    }
}

// ---------------- launch ----------------
extern "C" void kernel_launch(void* const* d_in, const int* in_sizes, int n_in,
                              void* d_out, int out_size)
{
    const float* x     = (const float*)d_in[0];
    const float* mask  = (const float*)d_in[1];
    const float* W_in  = (const float*)d_in[2];
    const float* b_in  = (const float*)d_in[3];
    const float* W1    = (const float*)d_in[4];
    const float* b1    = (const float*)d_in[5];
    const float* W2    = (const float*)d_in[6];
    const float* b2    = (const float*)d_in[7];
    const float* W_fin = (const float*)d_in[8];
    const float* b_fin = (const float*)d_in[9];
    float* out = (float*)d_out;

    float *dH, *dT, *dWLG, *dBLG, *dLG;
    cudaGetSymbolAddress((void**)&dH,   g_H);
    cudaGetSymbolAddress((void**)&dT,   g_T);
    cudaGetSymbolAddress((void**)&dWLG, g_WLG);
    cudaGetSymbolAddress((void**)&dBLG, g_BLG);
    cudaGetSymbolAddress((void**)&dLG,  g_LG);

    uint32_t kc0, kc1, kn0, kn1;
    threefry2x32(0u, 1234u, 0u, 0u, kc0, kc1);
    threefry2x32(0u, 1234u, 0u, 1u, kn0, kn1);

    static cudaStream_t sB = nullptr, sC = nullptr;
    static cudaEvent_t evStart, evLG, evG, evH, evM;
    if (!sB) {
        cudaStreamCreateWithFlags(&sB, cudaStreamNonBlocking);
        cudaStreamCreateWithFlags(&sC, cudaStreamNonBlocking);
        cudaEventCreateWithFlags(&evStart, cudaEventDisableTiming);
        cudaEventCreateWithFlags(&evLG,    cudaEventDisableTiming);
        cudaEventCreateWithFlags(&evG,     cudaEventDisableTiming);
        cudaEventCreateWithFlags(&evH,     cudaEventDisableTiming);
        cudaEventCreateWithFlags(&evM,     cudaEventDisableTiming);
        cudaFuncSetAttribute(musc_mma2,
                             cudaFuncAttributeMaxDynamicSharedMemorySize, 2 * 40960);
    }
    const int SMEM_MMA = 2 * 40960;

    cudaEventRecord(evStart, 0);
    cudaStreamWaitEvent(sB, evStart, 0);
    gather_lg<<<(HH * NLG + NLG + 255) / 256, 256, 0, sB>>>(W_fin, b_fin);
    cudaEventRecord(evLG, sB);
    gather_ms_t<<<dim3(NMS / 32, HH / 32), 256, 0, sB>>>(W_fin);
    gather_bms<<<(NMS + 255) / 256, 256, 0, sB>>>(b_fin);
    cudaEventRecord(evG, sB);

    dim3 blk(256);
    dim3 g1(HH / 128, BB / 64);
    sgemm_f32x2<false, false, true, false><<<g1, blk>>>(x, mask, W_in, b_in, dH, HH, 2 * DD);
    for (int l = 0; l < LL; l++) {
        sgemm_f32x2<true, false, false, false><<<g1, blk>>>(dH, nullptr, W1 + (size_t)l * HH * HH, b1 + l * HH, dT, HH, HH);
        if (l < LL - 1)
            sgemm_f32x2<true, true, false, false><<<g1, blk>>>(dT, nullptr, W2 + (size_t)l * HH * HH, b2 + l * HH, dH, HH, HH);
        else
            sgemm_f32x2<true, true, false, true><<<g1, blk>>>(dT, nullptr, W2 + (size_t)l * HH * HH, b2 + l * HH, dH, HH, HH);
    }
    cudaEventRecord(evH, 0);

    cudaStreamWaitEvent(sC, evH, 0);
    cudaStreamWaitEvent(sC, evG, 0);
    dim3 g3(NMS / 128, BB / 128);
    musc_mma2<<<g3, 256, SMEM_MMA, sC>>>();
    cudaEventRecord(evM, sC);

    cudaStreamWaitEvent(0, evLG, 0);
    dim3 g2(NLG / 128, BB / 64);
    sgemm_f32x2<false, false, false, false><<<g2, blk>>>(dH, nullptr, dWLG, dBLG, dLG, NLG, HH);

    cudaStreamWaitEvent(0, evM, 0);
    fused_tail<<<(BB * DD + 255) / 256, 256>>>(x, mask, out, kc0, kc1, kn0, kn1);
}

// round 12
// speedup vs baseline: 1.2577x; 1.2577x over previous
#include <cuda_runtime.h>
#include <cuda_bf16.h>
#include <cstdint>
#include <math.h>

// ---------------- problem constants ----------------
#define BB   4096
#define DD   256
#define HH   512
#define KK   10
#define HEADN 94
#define LL   4
#define SS   10
#define NLG  (DD * 10)     // 2560 logit cols
#define NMS  (DD * 20)     // 5120 mean/scale cols

typedef unsigned long long ull;

// ---------------- scratch ----------------
__device__ float g_H[BB * HH];
__device__ float g_T[BB * HH];
__device__ float g_WLG[HH * NLG];
__device__ float g_BLG[NLG];
__device__ float g_LG[(size_t)BB * NLG];
__device__ __nv_bfloat16 g_Hh[BB * HH];
__device__ __nv_bfloat16 g_Hl[BB * HH];
__device__ __nv_bfloat16 g_WBTh[NMS * HH];
__device__ __nv_bfloat16 g_WBTl[NMS * HH];
__device__ float g_BMS[NMS];
__device__ float g_MS[(size_t)BB * NMS];

// ---------------- f32x2 helpers ----------------
__device__ __forceinline__ ull pack2(float lo, float hi) {
    ull r; asm("mov.b64 %0, {%1, %2};" : "=l"(r) : "f"(lo), "f"(hi)); return r;
}
__device__ __forceinline__ ull fma2(ull a, ull b, ull c) {
    ull r; asm("fma.rn.f32x2 %0, %1, %2, %3;" : "=l"(r) : "l"(a), "l"(b), "l"(c)); return r;
}
__device__ __forceinline__ void unpack2(ull v, float& lo, float& hi) {
    asm("mov.b64 {%0, %1}, %2;" : "=f"(lo), "=f"(hi) : "l"(v));
}

// ---------------- cp.async ----------------
__device__ __forceinline__ void cp_async16(uint32_t dst, const void* src) {
    asm volatile("cp.async.cg.shared.global [%0], [%1], 16;" :: "r"(dst), "l"(src));
}
__device__ __forceinline__ void cp_commit() { asm volatile("cp.async.commit_group;"); }
__device__ __forceinline__ void cp_wait0()  { asm volatile("cp.async.wait_group 0;"); }
__device__ __forceinline__ void cp_wait1()  { asm volatile("cp.async.wait_group 1;"); }

// ---------------- mma / ldmatrix ----------------
__device__ __forceinline__ void ldsm4(uint32_t* r, uint32_t addr) {
    asm volatile("ldmatrix.sync.aligned.m8n8.x4.shared.b16 {%0,%1,%2,%3}, [%4];"
                 : "=r"(r[0]), "=r"(r[1]), "=r"(r[2]), "=r"(r[3]) : "r"(addr));
}
__device__ __forceinline__ void mma_bf16(float* c, const uint32_t* a, uint32_t b0, uint32_t b1) {
    asm volatile("mma.sync.aligned.m16n8k16.row.col.f32.bf16.bf16.f32 "
                 "{%0,%1,%2,%3}, {%4,%5,%6,%7}, {%8,%9}, {%0,%1,%2,%3};"
                 : "+f"(c[0]), "+f"(c[1]), "+f"(c[2]), "+f"(c[3])
                 : "r"(a[0]), "r"(a[1]), "r"(a[2]), "r"(a[3]), "r"(b0), "r"(b1));
}

// ---------------- threefry2x32 (bit-exact JAX) ----------------
__host__ __device__ __forceinline__ uint32_t rotl32(uint32_t x, int r) {
#if defined(__CUDA_ARCH__)
    return __funnelshift_l(x, x, r);
#else
    return (x << r) | (x >> (32 - r));
#endif
}

__host__ __device__ __forceinline__ void threefry2x32(
    uint32_t k0, uint32_t k1, uint32_t x0, uint32_t x1,
    uint32_t& o0, uint32_t& o1)
{
    uint32_t k2 = k0 ^ k1 ^ 0x1BD11BDAu;
    x0 += k0; x1 += k1;
    x0 += x1; x1 = rotl32(x1, 13); x1 ^= x0;
    x0 += x1; x1 = rotl32(x1, 15); x1 ^= x0;
    x0 += x1; x1 = rotl32(x1, 26); x1 ^= x0;
    x0 += x1; x1 = rotl32(x1, 6);  x1 ^= x0;
    x0 += k1; x1 += k2 + 1u;
    x0 += x1; x1 = rotl32(x1, 17); x1 ^= x0;
    x0 += x1; x1 = rotl32(x1, 29); x1 ^= x0;
    x0 += x1; x1 = rotl32(x1, 16); x1 ^= x0;
    x0 += x1; x1 = rotl32(x1, 24); x1 ^= x0;
    x0 += k2; x1 += k0 + 2u;
    x0 += x1; x1 = rotl32(x1, 13); x1 ^= x0;
    x0 += x1; x1 = rotl32(x1, 15); x1 ^= x0;
    x0 += x1; x1 = rotl32(x1, 26); x1 ^= x0;
    x0 += x1; x1 = rotl32(x1, 6);  x1 ^= x0;
    x0 += k0; x1 += k1 + 3u;
    x0 += x1; x1 = rotl32(x1, 17); x1 ^= x0;
    x0 += x1; x1 = rotl32(x1, 29); x1 ^= x0;
    x0 += x1; x1 = rotl32(x1, 16); x1 ^= x0;
    x0 += x1; x1 = rotl32(x1, 24); x1 ^= x0;
    x0 += k1; x1 += k2 + 4u;
    x0 += x1; x1 = rotl32(x1, 13); x1 ^= x0;
    x0 += x1; x1 = rotl32(x1, 15); x1 ^= x0;
    x0 += x1; x1 = rotl32(x1, 26); x1 ^= x0;
    x0 += x1; x1 = rotl32(x1, 6);  x1 ^= x0;
    x0 += k2; x1 += k0 + 5u;
    o0 = x0; o1 = x1;
}

__device__ __forceinline__ uint32_t tf_bits(uint32_t k0, uint32_t k1, uint32_t idx) {
    uint32_t o0, o1;
    threefry2x32(k0, k1, 0u, idx, o0, o1);
    return o0 ^ o1;
}

// ---------------- XLA-exact erfinv ----------------
__device__ __forceinline__ float erfinv_xla(float x) {
    float w = -logf((1.0f - x) * (1.0f + x));
    float p;
    if (w < 5.0f) {
        w -= 2.5f;
        p = 2.81022636e-08f;
        p = fmaf(p, w, 3.43273939e-07f);
        p = fmaf(p, w, -3.5233877e-06f);
        p = fmaf(p, w, -4.39150654e-06f);
        p = fmaf(p, w, 0.00021858087f);
        p = fmaf(p, w, -0.00125372503f);
        p = fmaf(p, w, -0.00417768164f);
        p = fmaf(p, w, 0.246640727f);
        p = fmaf(p, w, 1.50140941f);
    } else {
        w = sqrtf(w) - 3.0f;
        p = -0.000200214257f;
        p = fmaf(p, w, 0.000100950558f);
        p = fmaf(p, w, 0.00134934322f);
        p = fmaf(p, w, -0.00367342844f);
        p = fmaf(p, w, 0.00573950773f);
        p = fmaf(p, w, -0.0076224613f);
        p = fmaf(p, w, 0.00943887047f);
        p = fmaf(p, w, 1.00167406f);
        p = fmaf(p, w, 2.83297682f);
    }
    return p * x;
}

__device__ __forceinline__ float bits_to_unit(uint32_t b) {
    return __uint_as_float((b >> 9) | 0x3F800000u) - 1.0f;
}

// ---------------- gather kernels ----------------
__global__ void gather_lg(const float* __restrict__ Wf, const float* __restrict__ bf) {
    int t = blockIdx.x * blockDim.x + threadIdx.x;
    const int total = HH * NLG;
    if (t < total) {
        int n = t % NLG;
        int k = t / NLG;
        int d = n / 10, j = n - d * 10;
        g_WLG[t] = Wf[(size_t)k * (DD * HEADN) + d * HEADN + j];
    } else if (t < total + NLG) {
        int n = t - total;
        int d = n / 10, j = n - d * 10;
        g_BLG[n] = bf[d * HEADN + j];
    }
}

__global__ void gather_ms_t(const float* __restrict__ Wf) {
    __shared__ float tile[32][33];
    int n0 = blockIdx.x * 32;
    int k0 = blockIdx.y * 32;
    int tx = threadIdx.x & 31;
    int ty = threadIdx.x >> 5;
#pragma unroll
    for (int i = 0; i < 4; i++) {
        int k = k0 + ty + i * 8;
        int n = n0 + tx;
        int d = n / 20, r = n - d * 20;
        tile[ty + i * 8][tx] = Wf[(size_t)k * (DD * HEADN) + d * HEADN + 10 + r];
    }
    __syncthreads();
#pragma unroll
    for (int i = 0; i < 4; i++) {
        int n = n0 + ty + i * 8;
        int k = k0 + tx;
        float w = tile[tx][ty + i * 8];
        __nv_bfloat16 wh = __float2bfloat16(w);
        g_WBTh[(size_t)n * HH + k] = wh;
        g_WBTl[(size_t)n * HH + k] = __float2bfloat16(w - __bfloat162float(wh));
    }
}

__global__ void gather_bms(const float* __restrict__ bf) {
    int n = blockIdx.x * blockDim.x + threadIdx.x;
    if (n >= NMS) return;
    int d = n / 20, r = n - d * 20;
    g_BMS[n] = bf[d * HEADN + 10 + r];
}

// ---------------- exact fp32 SGEMM (R10 config: 64x128, BK=16, 128 thr, 8x8) ----
template <bool RELU_A, bool ADD_C, bool PREP, bool BF16OUT>
__global__ __launch_bounds__(128, 3) void sgemm_f32x2(
    const float* __restrict__ A, const float* __restrict__ Xm,
    const float* __restrict__ Bm,
    const float* __restrict__ bias, float* __restrict__ C,
    int N, int Kd)
{
    __shared__ float As[2][16][68];
    __shared__ float Bs[2][16][128];

    const int t  = threadIdx.x;
    const int bm = blockIdx.y * 64;
    const int bn = blockIdx.x * 128;
    const int tx = t & 15;
    const int ty = t >> 4;

    const int arow = t >> 1;
    const int ak   = (t & 1) * 8;
    const int brow = t >> 5;
    const int bcol = (t & 31) * 4;

    ull acc2[8][4];
#pragma unroll
    for (int i = 0; i < 8; i++)
#pragma unroll
        for (int j = 0; j < 4; j++) acc2[i][j] = 0ull;

    float4 aR0, aR1, bR[4];

    auto loadG = [&](int k0) {
        if (PREP) {
            int col0 = k0 + ak;
            const float* xrow = A  + (size_t)(bm + arow) * DD;
            const float* mrow = Xm + (size_t)(bm + arow) * DD;
            if (col0 < DD) {
                float4 xv = *reinterpret_cast<const float4*>(xrow + col0);
                float4 mv = *reinterpret_cast<const float4*>(mrow + col0);
                aR0 = make_float4(xv.x * mv.x, xv.y * mv.y, xv.z * mv.z, xv.w * mv.w);
                xv = *reinterpret_cast<const float4*>(xrow + col0 + 4);
                mv = *reinterpret_cast<const float4*>(mrow + col0 + 4);
                aR1 = make_float4(xv.x * mv.x, xv.y * mv.y, xv.z * mv.z, xv.w * mv.w);
            } else {
                aR0 = *reinterpret_cast<const float4*>(mrow + col0 - DD);
                aR1 = *reinterpret_cast<const float4*>(mrow + col0 - DD + 4);
            }
        } else {
            const float* Ap = A + (size_t)(bm + arow) * Kd + k0 + ak;
            aR0 = *reinterpret_cast<const float4*>(Ap);
            aR1 = *reinterpret_cast<const float4*>(Ap + 4);
            if (RELU_A) {
                aR0.x = fmaxf(aR0.x, 0.f); aR0.y = fmaxf(aR0.y, 0.f);
                aR0.z = fmaxf(aR0.z, 0.f); aR0.w = fmaxf(aR0.w, 0.f);
                aR1.x = fmaxf(aR1.x, 0.f); aR1.y = fmaxf(aR1.y, 0.f);
                aR1.z = fmaxf(aR1.z, 0.f); aR1.w = fmaxf(aR1.w, 0.f);
            }
        }
#pragma unroll
        for (int i = 0; i < 4; i++)
            bR[i] = *reinterpret_cast<const float4*>(Bm + (size_t)(k0 + brow + 4 * i) * N + bn + bcol);
    };
    auto storeS = [&](int p) {
        As[p][ak + 0][arow] = aR0.x;
        As[p][ak + 1][arow] = aR0.y;
        As[p][ak + 2][arow] = aR0.z;
        As[p][ak + 3][arow] = aR0.w;
        As[p][ak + 4][arow] = aR1.x;
        As[p][ak + 5][arow] = aR1.y;
        As[p][ak + 6][arow] = aR1.z;
        As[p][ak + 7][arow] = aR1.w;
#pragma unroll
        for (int i = 0; i < 4; i++)
            *reinterpret_cast<float4*>(&Bs[p][brow + 4 * i][bcol]) = bR[i];
    };

    loadG(0);
    storeS(0);
    __syncthreads();

    const int T = Kd >> 4;
    int p = 0;
#pragma unroll 1
    for (int tk = 0; tk < T; tk++) {
        if (tk + 1 < T) loadG((tk + 1) << 4);
#pragma unroll
        for (int kk = 0; kk < 16; kk++) {
            float a[8];
            *reinterpret_cast<float4*>(a)     = *reinterpret_cast<const float4*>(&As[p][kk][ty * 8]);
            *reinterpret_cast<float4*>(a + 4) = *reinterpret_cast<const float4*>(&As[p][kk][ty * 8 + 4]);
            ulonglong2 bq0 = *reinterpret_cast<const ulonglong2*>(&Bs[p][kk][tx * 8]);
            ulonglong2 bq1 = *reinterpret_cast<const ulonglong2*>(&Bs[p][kk][tx * 8 + 4]);
#pragma unroll
            for (int i = 0; i < 8; i++) {
                ull a2 = pack2(a[i], a[i]);
                acc2[i][0] = fma2(a2, bq0.x, acc2[i][0]);
                acc2[i][1] = fma2(a2, bq0.y, acc2[i][1]);
                acc2[i][2] = fma2(a2, bq1.x, acc2[i][2]);
                acc2[i][3] = fma2(a2, bq1.y, acc2[i][3]);
            }
        }
        if (tk + 1 < T) {
            storeS(p ^ 1);
            __syncthreads();
            p ^= 1;
        }
    }

    float4 bia0 = *reinterpret_cast<const float4*>(bias + bn + tx * 8);
    float4 bia1 = *reinterpret_cast<const float4*>(bias + bn + tx * 8 + 4);
#pragma unroll
    for (int i = 0; i < 8; i++) {
        size_t roff = (size_t)(bm + ty * 8 + i) * N + bn + tx * 8;
        float* crow = C + roff;
        float v[8];
        unpack2(acc2[i][0], v[0], v[1]);
        unpack2(acc2[i][1], v[2], v[3]);
        unpack2(acc2[i][2], v[4], v[5]);
        unpack2(acc2[i][3], v[6], v[7]);
        float4 r0, r1;
        r0.x = v[0] + bia0.x; r0.y = v[1] + bia0.y;
        r0.z = v[2] + bia0.z; r0.w = v[3] + bia0.w;
        r1.x = v[4] + bia1.x; r1.y = v[5] + bia1.y;
        r1.z = v[6] + bia1.z; r1.w = v[7] + bia1.w;
        if (ADD_C) {
            float4 c0 = *reinterpret_cast<const float4*>(crow);
            float4 c1 = *reinterpret_cast<const float4*>(crow + 4);
            r0.x += c0.x; r0.y += c0.y; r0.z += c0.z; r0.w += c0.w;
            r1.x += c1.x; r1.y += c1.y; r1.z += c1.z; r1.w += c1.w;
        }
        *reinterpret_cast<float4*>(crow)     = r0;
        *reinterpret_cast<float4*>(crow + 4) = r1;
        if (BF16OUT) {
            float rv[8] = {r0.x, r0.y, r0.z, r0.w, r1.x, r1.y, r1.z, r1.w};
            __nv_bfloat16 hh[8], hl[8];
#pragma unroll
            for (int m = 0; m < 8; m++) {
                hh[m] = __float2bfloat16(rv[m]);
                hl[m] = __float2bfloat16(rv[m] - __bfloat162float(hh[m]));
            }
            *reinterpret_cast<uint4*>(g_Hh + roff) = *reinterpret_cast<uint4*>(hh);
            *reinterpret_cast<uint4*>(g_Hl + roff) = *reinterpret_cast<uint4*>(hl);
        }
    }
}

// ---------------- bf16-split HMMA GEMM v2 ----------------
__global__ __launch_bounds__(256, 2) void musc_mma2() {
    extern __shared__ char smc[];
    const uint32_t smbase = (uint32_t)__cvta_generic_to_shared(smc);

    const int t = threadIdx.x;
    const int w = t >> 5;
    const int l = t & 31;
    const int wm = w & 3;
    const int wn = w >> 2;
    const int bn = blockIdx.x * 128;
    const int bm = blockIdx.y * 128;

    const int tile = t >> 6;
    const int sub  = t & 63;
    const __nv_bfloat16* gsrc =
        (tile == 0) ? g_Hh : (tile == 1) ? g_Hl : (tile == 2) ? g_WBTh : g_WBTl;
    const int gbase = (tile < 2) ? bm : bn;

    auto issue = [&](int k0, int p) {
        uint32_t dbase = smbase + (uint32_t)(p * 40960 + tile * 10240);
#pragma unroll
        for (int rr = 0; rr < 2; rr++) {
            int row = sub * 2 + rr;
            const __nv_bfloat16* s = gsrc + (size_t)(gbase + row) * HH + k0;
            uint32_t dst = dbase + (uint32_t)(row * 80);
            cp_async16(dst,      s);
            cp_async16(dst + 16, reinterpret_cast<const char*>(s) + 16);
            cp_async16(dst + 32, reinterpret_cast<const char*>(s) + 32);
            cp_async16(dst + 48, reinterpret_cast<const char*>(s) + 48);
        }
    };

    const uint32_t a_off0 = (uint32_t)((wm * 32 +      (l & 15)) * 80 + ((l >> 4) << 4));
    const uint32_t a_off1 = (uint32_t)((wm * 32 + 16 + (l & 15)) * 80 + ((l >> 4) << 4));
    const uint32_t b_row  = (uint32_t)((l & 7) + ((l >> 4) & 1) * 8);
    const uint32_t b_koff = (uint32_t)(((l >> 3) & 1) << 4);

    float acc[2][8][4];
#pragma unroll
    for (int f = 0; f < 2; f++)
#pragma unroll
        for (int i = 0; i < 8; i++)
#pragma unroll
            for (int j = 0; j < 4; j++) acc[f][i][j] = 0.0f;

    issue(0, 0);
    cp_commit();

    const int T = HH / 32;
    int p = 0;
#pragma unroll 1
    for (int tk = 0; tk < T; tk++) {
        if (tk + 1 < T) {
            issue((tk + 1) * 32, p ^ 1);
            cp_commit();
            cp_wait1();
        } else {
            cp_wait0();
        }
        __syncthreads();

        uint32_t base = smbase + (uint32_t)(p * 40960);
#pragma unroll
        for (int ks = 0; ks < 2; ks++) {
            uint32_t ksb = (uint32_t)(ks * 32);
            uint32_t ah[2][4], al[2][4];
            ldsm4(ah[0], base + a_off0 + ksb);
            ldsm4(ah[1], base + a_off1 + ksb);
            ldsm4(al[0], base + 10240 + a_off0 + ksb);
            ldsm4(al[1], base + 10240 + a_off1 + ksb);
#pragma unroll
            for (int q = 0; q < 4; q++) {
                uint32_t boff = (uint32_t)((wn * 64 + q * 16 + b_row) * 80) + b_koff + ksb;
                uint32_t bh[4], bl[4];
                ldsm4(bh, base + 20480 + boff);
                ldsm4(bl, base + 30720 + boff);
#pragma unroll
                for (int f = 0; f < 2; f++) {
#pragma unroll
                    for (int h = 0; h < 2; h++) {
                        float* a = acc[f][2 * q + h];
                        mma_bf16(a, ah[f], bh[2 * h], bh[2 * h + 1]);
                        mma_bf16(a, ah[f], bl[2 * h], bl[2 * h + 1]);
                        mma_bf16(a, al[f], bh[2 * h], bh[2 * h + 1]);
                    }
                }
            }
        }
        __syncthreads();
        p ^= 1;
    }

    const int g  = l >> 2;
    const int tt = l & 3;
#pragma unroll
    for (int f = 0; f < 2; f++) {
        int m0 = bm + wm * 32 + f * 16 + g;
#pragma unroll
        for (int nb = 0; nb < 8; nb++) {
            int n = bn + wn * 64 + nb * 8 + tt * 2;
            float2 bia = *reinterpret_cast<const float2*>(g_BMS + n);
            float2 v0 = make_float2(acc[f][nb][0] + bia.x, acc[f][nb][1] + bia.y);
            float2 v1 = make_float2(acc[f][nb][2] + bia.x, acc[f][nb][3] + bia.y);
            *reinterpret_cast<float2*>(g_MS + (size_t)m0 * NMS + n)       = v0;
            *reinterpret_cast<float2*>(g_MS + (size_t)(m0 + 8) * NMS + n) = v1;
        }
    }
}

// ---------------- fused tail (exponential-race argmax + exact fallback) ----
__global__ void fused_tail(const float* __restrict__ x, const float* __restrict__ mask,
                           float* __restrict__ out,
                           uint32_t kc0, uint32_t kc1, uint32_t kn0, uint32_t kn1)
{
    int t = blockIdx.x * blockDim.x + threadIdx.x;
    if (t >= BB * DD) return;
    int b = t >> 8;
    int d = t & (DD - 1);

    const float* lrow = g_LG + (size_t)b * NLG + d * 10;
    const float* mrow = g_MS + (size_t)b * NMS + d * 20;
    float lg[KK], mu[KK], sc[KK];
#pragma unroll
    for (int j = 0; j < KK; j++) lg[j] = lrow[j];
#pragma unroll
    for (int j = 0; j < KK; j++) mu[j] = mrow[j];
#pragma unroll
    for (int j = 0; j < KK; j++) {
        float v = mrow[10 + j];
        sc[j] = fmaxf(v, 0.0f) + log1pf(expf(-fabsf(v))) + 0.001f;
    }
    float q  = 1.0f - mask[t];
    float xu = x[t] * q;

    float mx = lg[0];
#pragma unroll
    for (int j = 1; j < KK; j++) mx = fmaxf(mx, lg[j]);
    float se = 0.0f;
#pragma unroll
    for (int j = 0; j < KK; j++) se += expf(lg[j] - mx);
    float lse = logf(se);

    float term[KK];
    float m2v = -1e30f;
#pragma unroll
    for (int j = 0; j < KK; j++) {
        float z   = (xu - mu[j]) / sc[j];
        float cll = -0.5f * z * z - logf(sc[j]) - 0.9189385332046727f;
        term[j] = (lg[j] - mx - lse) + cll;
        m2v = fmaxf(m2v, term[j]);
    }
    float s2 = 0.0f;
#pragma unroll
    for (int j = 0; j < KK; j++) s2 += expf(term[j] - m2v);
    out[t] = (m2v + logf(s2)) * q;

    float pm = 0.0f;
#pragma unroll
    for (int j = 0; j < KK; j++) pm += (expf(lg[j] - mx) / se) * mu[j];
    out[BB * DD + SS * BB * DD + t] = pm * q;

    // surrogate weights (per-j, reused for all 10 samples)
    float E[KK];
#pragma unroll
    for (int j = 0; j < KK; j++) E[j] = __expf(-lg[j]);

    float* smp = out + BB * DD;
    const float TINY = 1.17549435e-38f;

#pragma unroll 1
    for (int s = 0; s < SS; s++) {
        uint32_t idx_e = (uint32_t)(s * BB + b) * DD + (uint32_t)d;
        uint32_t base  = idx_e * KK;
        float e[KK];
        float m1 = 3.4e38f, m2 = 3.4e38f;
        int a = 0;
#pragma unroll
        for (int j = 0; j < KK; j++) {
            uint32_t bits = tf_bits(kc0, kc1, base + j);
            float f = bits_to_unit(bits);
            float u = fmaxf(TINY, f + TINY);
            e[j] = -logf(u);                 // exponential variate
            float mm = e[j] * E[j];          // surrogate race value
            if (mm < m1) { m2 = m1; m1 = mm; a = j; }
            else if (mm < m2) { m2 = mm; }
        }
        // guard: if runner-up within 1e-3 relative, recompute exact argmax
        if (!(m2 > fmaf(m1, 1e-3f, m1))) {
            float best = -1e30f;
            a = 0;
#pragma unroll
            for (int j = 0; j < KK; j++) {
                float g = -logf(e[j]);       // exact gumbel (same bits as R8)
                float v = lg[j] + g;
                if (v > best) { best = v; a = j; }
            }
        }
        float mua = 0.f, sca = 0.f;
#pragma unroll
        for (int j = 0; j < KK; j++) {
            if (a == j) { mua = mu[j]; sca = sc[j]; }
        }
        uint32_t ebits = tf_bits(kn0, kn1, idx_e);
        const float LO = -0.99999994f;
        float u = fmaxf(LO, fmaf(bits_to_unit(ebits), 2.0f, LO));
        float eps = 1.41421356237309515f * erfinv_xla(u);
        smp[(b * SS + s) * DD + d] = (mua + sca * eps) * q;
    }
}

// ---------------- launch ----------------
extern "C" void kernel_launch(void* const* d_in, const int* in_sizes, int n_in,
                              void* d_out, int out_size)
{
    const float* x     = (const float*)d_in[0];
    const float* mask  = (const float*)d_in[1];
    const float* W_in  = (const float*)d_in[2];
    const float* b_in  = (const float*)d_in[3];
    const float* W1    = (const float*)d_in[4];
    const float* b1    = (const float*)d_in[5];
    const float* W2    = (const float*)d_in[6];
    const float* b2    = (const float*)d_in[7];
    const float* W_fin = (const float*)d_in[8];
    const float* b_fin = (const float*)d_in[9];
    float* out = (float*)d_out;

    float *dH, *dT, *dWLG, *dBLG, *dLG;
    cudaGetSymbolAddress((void**)&dH,   g_H);
    cudaGetSymbolAddress((void**)&dT,   g_T);
    cudaGetSymbolAddress((void**)&dWLG, g_WLG);
    cudaGetSymbolAddress((void**)&dBLG, g_BLG);
    cudaGetSymbolAddress((void**)&dLG,  g_LG);

    uint32_t kc0, kc1, kn0, kn1;
    threefry2x32(0u, 1234u, 0u, 0u, kc0, kc1);
    threefry2x32(0u, 1234u, 0u, 1u, kn0, kn1);

    static cudaStream_t sB = nullptr, sC = nullptr;
    static cudaEvent_t evStart, evLG, evG, evH, evM;
    if (!sB) {
        cudaStreamCreateWithFlags(&sB, cudaStreamNonBlocking);
        cudaStreamCreateWithFlags(&sC, cudaStreamNonBlocking);
        cudaEventCreateWithFlags(&evStart, cudaEventDisableTiming);
        cudaEventCreateWithFlags(&evLG,    cudaEventDisableTiming);
        cudaEventCreateWithFlags(&evG,     cudaEventDisableTiming);
        cudaEventCreateWithFlags(&evH,     cudaEventDisableTiming);
        cudaEventCreateWithFlags(&evM,     cudaEventDisableTiming);
        cudaFuncSetAttribute(musc_mma2,
                             cudaFuncAttributeMaxDynamicSharedMemorySize, 2 * 40960);
    }
    const int SMEM_MMA = 2 * 40960;

    cudaEventRecord(evStart, 0);
    cudaStreamWaitEvent(sB, evStart, 0);
    gather_lg<<<(HH * NLG + NLG + 255) / 256, 256, 0, sB>>>(W_fin, b_fin);
    cudaEventRecord(evLG, sB);
    gather_ms_t<<<dim3(NMS / 32, HH / 32), 256, 0, sB>>>(W_fin);
    gather_bms<<<(NMS + 255) / 256, 256, 0, sB>>>(b_fin);
    cudaEventRecord(evG, sB);

    dim3 blk(128);
    dim3 g1(HH / 128, BB / 64);
    sgemm_f32x2<false, false, true, false><<<g1, blk>>>(x, mask, W_in, b_in, dH, HH, 2 * DD);
    for (int l = 0; l < LL; l++) {
        sgemm_f32x2<true, false, false, false><<<g1, blk>>>(dH, nullptr, W1 + (size_t)l * HH * HH, b1 + l * HH, dT, HH, HH);
        if (l < LL - 1)
            sgemm_f32x2<true, true, false, false><<<g1, blk>>>(dT, nullptr, W2 + (size_t)l * HH * HH, b2 + l * HH, dH, HH, HH);
        else
            sgemm_f32x2<true, true, false, true><<<g1, blk>>>(dT, nullptr, W2 + (size_t)l * HH * HH, b2 + l * HH, dH, HH, HH);
    }
    cudaEventRecord(evH, 0);

    cudaStreamWaitEvent(sC, evH, 0);
    cudaStreamWaitEvent(sC, evG, 0);
    dim3 g3(NMS / 128, BB / 128);
    musc_mma2<<<g3, 256, SMEM_MMA, sC>>>();
    cudaEventRecord(evM, sC);

    cudaStreamWaitEvent(0, evLG, 0);
    dim3 g2(NLG / 128, BB / 64);
    sgemm_f32x2<false, false, false, false><<<g2, blk>>>(dH, nullptr, dWLG, dBLG, dLG, NLG, HH);

    cudaStreamWaitEvent(0, evM, 0);
    fused_tail<<<(BB * DD + 255) / 256, 256>>>(x, mask, out, kc0, kc1, kn0, kn1);
}

// round 13
// speedup vs baseline: 1.2926x; 1.0277x over previous
#include <cuda_runtime.h>
#include <cuda_bf16.h>
#include <cstdint>
#include <math.h>

// ---------------- problem constants ----------------
#define BB   4096
#define DD   256
#define HH   512
#define KK   10
#define HEADN 94
#define LL   4
#define SS   10
#define NLG  (DD * 10)     // 2560 logit cols
#define NMS  (DD * 20)     // 5120 mean/scale cols
#define NCHUNK 4
#define DCH  (DD / NCHUNK) // 64 d per chunk

typedef unsigned long long ull;

// ---------------- scratch ----------------
__device__ float g_H[BB * HH];
__device__ float g_T[BB * HH];
__device__ float g_WLG[HH * NLG];
__device__ float g_BLG[NLG];
__device__ float g_LG[(size_t)BB * NLG];
__device__ __nv_bfloat16 g_Hh[BB * HH];
__device__ __nv_bfloat16 g_Hl[BB * HH];
__device__ __nv_bfloat16 g_WBTh[NMS * HH];
__device__ __nv_bfloat16 g_WBTl[NMS * HH];
__device__ float g_BMS[NMS];
__device__ float g_MS[(size_t)BB * NMS];

// ---------------- f32x2 helpers ----------------
__device__ __forceinline__ ull pack2(float lo, float hi) {
    ull r; asm("mov.b64 %0, {%1, %2};" : "=l"(r) : "f"(lo), "f"(hi)); return r;
}
__device__ __forceinline__ ull fma2(ull a, ull b, ull c) {
    ull r; asm("fma.rn.f32x2 %0, %1, %2, %3;" : "=l"(r) : "l"(a), "l"(b), "l"(c)); return r;
}
__device__ __forceinline__ void unpack2(ull v, float& lo, float& hi) {
    asm("mov.b64 {%0, %1}, %2;" : "=f"(lo), "=f"(hi) : "l"(v));
}

// ---------------- cp.async ----------------
__device__ __forceinline__ void cp_async16(uint32_t dst, const void* src) {
    asm volatile("cp.async.cg.shared.global [%0], [%1], 16;" :: "r"(dst), "l"(src));
}
__device__ __forceinline__ void cp_commit() { asm volatile("cp.async.commit_group;"); }
__device__ __forceinline__ void cp_wait0()  { asm volatile("cp.async.wait_group 0;"); }
__device__ __forceinline__ void cp_wait1()  { asm volatile("cp.async.wait_group 1;"); }

// ---------------- mma / ldmatrix ----------------
__device__ __forceinline__ void ldsm4(uint32_t* r, uint32_t addr) {
    asm volatile("ldmatrix.sync.aligned.m8n8.x4.shared.b16 {%0,%1,%2,%3}, [%4];"
                 : "=r"(r[0]), "=r"(r[1]), "=r"(r[2]), "=r"(r[3]) : "r"(addr));
}
__device__ __forceinline__ void mma_bf16(float* c, const uint32_t* a, uint32_t b0, uint32_t b1) {
    asm volatile("mma.sync.aligned.m16n8k16.row.col.f32.bf16.bf16.f32 "
                 "{%0,%1,%2,%3}, {%4,%5,%6,%7}, {%8,%9}, {%0,%1,%2,%3};"
                 : "+f"(c[0]), "+f"(c[1]), "+f"(c[2]), "+f"(c[3])
                 : "r"(a[0]), "r"(a[1]), "r"(a[2]), "r"(a[3]), "r"(b0), "r"(b1));
}

// ---------------- threefry2x32 (bit-exact JAX) ----------------
__host__ __device__ __forceinline__ uint32_t rotl32(uint32_t x, int r) {
#if defined(__CUDA_ARCH__)
    return __funnelshift_l(x, x, r);
#else
    return (x << r) | (x >> (32 - r));
#endif
}

__host__ __device__ __forceinline__ void threefry2x32(
    uint32_t k0, uint32_t k1, uint32_t x0, uint32_t x1,
    uint32_t& o0, uint32_t& o1)
{
    uint32_t k2 = k0 ^ k1 ^ 0x1BD11BDAu;
    x0 += k0; x1 += k1;
    x0 += x1; x1 = rotl32(x1, 13); x1 ^= x0;
    x0 += x1; x1 = rotl32(x1, 15); x1 ^= x0;
    x0 += x1; x1 = rotl32(x1, 26); x1 ^= x0;
    x0 += x1; x1 = rotl32(x1, 6);  x1 ^= x0;
    x0 += k1; x1 += k2 + 1u;
    x0 += x1; x1 = rotl32(x1, 17); x1 ^= x0;
    x0 += x1; x1 = rotl32(x1, 29); x1 ^= x0;
    x0 += x1; x1 = rotl32(x1, 16); x1 ^= x0;
    x0 += x1; x1 = rotl32(x1, 24); x1 ^= x0;
    x0 += k2; x1 += k0 + 2u;
    x0 += x1; x1 = rotl32(x1, 13); x1 ^= x0;
    x0 += x1; x1 = rotl32(x1, 15); x1 ^= x0;
    x0 += x1; x1 = rotl32(x1, 26); x1 ^= x0;
    x0 += x1; x1 = rotl32(x1, 6);  x1 ^= x0;
    x0 += k0; x1 += k1 + 3u;
    x0 += x1; x1 = rotl32(x1, 17); x1 ^= x0;
    x0 += x1; x1 = rotl32(x1, 29); x1 ^= x0;
    x0 += x1; x1 = rotl32(x1, 16); x1 ^= x0;
    x0 += x1; x1 = rotl32(x1, 24); x1 ^= x0;
    x0 += k1; x1 += k2 + 4u;
    x0 += x1; x1 = rotl32(x1, 13); x1 ^= x0;
    x0 += x1; x1 = rotl32(x1, 15); x1 ^= x0;
    x0 += x1; x1 = rotl32(x1, 26); x1 ^= x0;
    x0 += x1; x1 = rotl32(x1, 6);  x1 ^= x0;
    x0 += k2; x1 += k0 + 5u;
    o0 = x0; o1 = x1;
}

__device__ __forceinline__ uint32_t tf_bits(uint32_t k0, uint32_t k1, uint32_t idx) {
    uint32_t o0, o1;
    threefry2x32(k0, k1, 0u, idx, o0, o1);
    return o0 ^ o1;
}

// ---------------- XLA-exact erfinv ----------------
__device__ __forceinline__ float erfinv_xla(float x) {
    float w = -logf((1.0f - x) * (1.0f + x));
    float p;
    if (w < 5.0f) {
        w -= 2.5f;
        p = 2.81022636e-08f;
        p = fmaf(p, w, 3.43273939e-07f);
        p = fmaf(p, w, -3.5233877e-06f);
        p = fmaf(p, w, -4.39150654e-06f);
        p = fmaf(p, w, 0.00021858087f);
        p = fmaf(p, w, -0.00125372503f);
        p = fmaf(p, w, -0.00417768164f);
        p = fmaf(p, w, 0.246640727f);
        p = fmaf(p, w, 1.50140941f);
    } else {
        w = sqrtf(w) - 3.0f;
        p = -0.000200214257f;
        p = fmaf(p, w, 0.000100950558f);
        p = fmaf(p, w, 0.00134934322f);
        p = fmaf(p, w, -0.00367342844f);
        p = fmaf(p, w, 0.00573950773f);
        p = fmaf(p, w, -0.0076224613f);
        p = fmaf(p, w, 0.00943887047f);
        p = fmaf(p, w, 1.00167406f);
        p = fmaf(p, w, 2.83297682f);
    }
    return p * x;
}

__device__ __forceinline__ float bits_to_unit(uint32_t b) {
    return __uint_as_float((b >> 9) | 0x3F800000u) - 1.0f;
}

// ---------------- gather kernels ----------------
__global__ void gather_lg(const float* __restrict__ Wf, const float* __restrict__ bf) {
    int t = blockIdx.x * blockDim.x + threadIdx.x;
    const int total = HH * NLG;
    if (t < total) {
        int n = t % NLG;
        int k = t / NLG;
        int d = n / 10, j = n - d * 10;
        g_WLG[t] = Wf[(size_t)k * (DD * HEADN) + d * HEADN + j];
    } else if (t < total + NLG) {
        int n = t - total;
        int d = n / 10, j = n - d * 10;
        g_BLG[n] = bf[d * HEADN + j];
    }
}

__global__ void gather_ms_t(const float* __restrict__ Wf) {
    __shared__ float tile[32][33];
    int n0 = blockIdx.x * 32;
    int k0 = blockIdx.y * 32;
    int tx = threadIdx.x & 31;
    int ty = threadIdx.x >> 5;
#pragma unroll
    for (int i = 0; i < 4; i++) {
        int k = k0 + ty + i * 8;
        int n = n0 + tx;
        int d = n / 20, r = n - d * 20;
        tile[ty + i * 8][tx] = Wf[(size_t)k * (DD * HEADN) + d * HEADN + 10 + r];
    }
    __syncthreads();
#pragma unroll
    for (int i = 0; i < 4; i++) {
        int n = n0 + ty + i * 8;
        int k = k0 + tx;
        float w = tile[tx][ty + i * 8];
        __nv_bfloat16 wh = __float2bfloat16(w);
        g_WBTh[(size_t)n * HH + k] = wh;
        g_WBTl[(size_t)n * HH + k] = __float2bfloat16(w - __bfloat162float(wh));
    }
}

__global__ void gather_bms(const float* __restrict__ bf) {
    int n = blockIdx.x * blockDim.x + threadIdx.x;
    if (n >= NMS) return;
    int d = n / 20, r = n - d * 20;
    g_BMS[n] = bf[d * HEADN + 10 + r];
}

// ---------------- exact fp32 SGEMM (64x128, BK=16, 128 thr, 8x8) ----------------
template <bool RELU_A, bool ADD_C, bool PREP, bool BF16OUT>
__global__ __launch_bounds__(128, 3) void sgemm_f32x2(
    const float* __restrict__ A, const float* __restrict__ Xm,
    const float* __restrict__ Bm,
    const float* __restrict__ bias, float* __restrict__ C,
    int N, int Kd)
{
    __shared__ float As[2][16][68];
    __shared__ float Bs[2][16][128];

    const int t  = threadIdx.x;
    const int bm = blockIdx.y * 64;
    const int bn = blockIdx.x * 128;
    const int tx = t & 15;
    const int ty = t >> 4;

    const int arow = t >> 1;
    const int ak   = (t & 1) * 8;
    const int brow = t >> 5;
    const int bcol = (t & 31) * 4;

    ull acc2[8][4];
#pragma unroll
    for (int i = 0; i < 8; i++)
#pragma unroll
        for (int j = 0; j < 4; j++) acc2[i][j] = 0ull;

    float4 aR0, aR1, bR[4];

    auto loadG = [&](int k0) {
        if (PREP) {
            int col0 = k0 + ak;
            const float* xrow = A  + (size_t)(bm + arow) * DD;
            const float* mrow = Xm + (size_t)(bm + arow) * DD;
            if (col0 < DD) {
                float4 xv = *reinterpret_cast<const float4*>(xrow + col0);
                float4 mv = *reinterpret_cast<const float4*>(mrow + col0);
                aR0 = make_float4(xv.x * mv.x, xv.y * mv.y, xv.z * mv.z, xv.w * mv.w);
                xv = *reinterpret_cast<const float4*>(xrow + col0 + 4);
                mv = *reinterpret_cast<const float4*>(mrow + col0 + 4);
                aR1 = make_float4(xv.x * mv.x, xv.y * mv.y, xv.z * mv.z, xv.w * mv.w);
            } else {
                aR0 = *reinterpret_cast<const float4*>(mrow + col0 - DD);
                aR1 = *reinterpret_cast<const float4*>(mrow + col0 - DD + 4);
            }
        } else {
            const float* Ap = A + (size_t)(bm + arow) * Kd + k0 + ak;
            aR0 = *reinterpret_cast<const float4*>(Ap);
            aR1 = *reinterpret_cast<const float4*>(Ap + 4);
            if (RELU_A) {
                aR0.x = fmaxf(aR0.x, 0.f); aR0.y = fmaxf(aR0.y, 0.f);
                aR0.z = fmaxf(aR0.z, 0.f); aR0.w = fmaxf(aR0.w, 0.f);
                aR1.x = fmaxf(aR1.x, 0.f); aR1.y = fmaxf(aR1.y, 0.f);
                aR1.z = fmaxf(aR1.z, 0.f); aR1.w = fmaxf(aR1.w, 0.f);
            }
        }
#pragma unroll
        for (int i = 0; i < 4; i++)
            bR[i] = *reinterpret_cast<const float4*>(Bm + (size_t)(k0 + brow + 4 * i) * N + bn + bcol);
    };
    auto storeS = [&](int p) {
        As[p][ak + 0][arow] = aR0.x;
        As[p][ak + 1][arow] = aR0.y;
        As[p][ak + 2][arow] = aR0.z;
        As[p][ak + 3][arow] = aR0.w;
        As[p][ak + 4][arow] = aR1.x;
        As[p][ak + 5][arow] = aR1.y;
        As[p][ak + 6][arow] = aR1.z;
        As[p][ak + 7][arow] = aR1.w;
#pragma unroll
        for (int i = 0; i < 4; i++)
            *reinterpret_cast<float4*>(&Bs[p][brow + 4 * i][bcol]) = bR[i];
    };

    loadG(0);
    storeS(0);
    __syncthreads();

    const int T = Kd >> 4;
    int p = 0;
#pragma unroll 1
    for (int tk = 0; tk < T; tk++) {
        if (tk + 1 < T) loadG((tk + 1) << 4);
#pragma unroll
        for (int kk = 0; kk < 16; kk++) {
            float a[8];
            *reinterpret_cast<float4*>(a)     = *reinterpret_cast<const float4*>(&As[p][kk][ty * 8]);
            *reinterpret_cast<float4*>(a + 4) = *reinterpret_cast<const float4*>(&As[p][kk][ty * 8 + 4]);
            ulonglong2 bq0 = *reinterpret_cast<const ulonglong2*>(&Bs[p][kk][tx * 8]);
            ulonglong2 bq1 = *reinterpret_cast<const ulonglong2*>(&Bs[p][kk][tx * 8 + 4]);
#pragma unroll
            for (int i = 0; i < 8; i++) {
                ull a2 = pack2(a[i], a[i]);
                acc2[i][0] = fma2(a2, bq0.x, acc2[i][0]);
                acc2[i][1] = fma2(a2, bq0.y, acc2[i][1]);
                acc2[i][2] = fma2(a2, bq1.x, acc2[i][2]);
                acc2[i][3] = fma2(a2, bq1.y, acc2[i][3]);
            }
        }
        if (tk + 1 < T) {
            storeS(p ^ 1);
            __syncthreads();
            p ^= 1;
        }
    }

    float4 bia0 = *reinterpret_cast<const float4*>(bias + bn + tx * 8);
    float4 bia1 = *reinterpret_cast<const float4*>(bias + bn + tx * 8 + 4);
#pragma unroll
    for (int i = 0; i < 8; i++) {
        size_t roff = (size_t)(bm + ty * 8 + i) * N + bn + tx * 8;
        float* crow = C + roff;
        float v[8];
        unpack2(acc2[i][0], v[0], v[1]);
        unpack2(acc2[i][1], v[2], v[3]);
        unpack2(acc2[i][2], v[4], v[5]);
        unpack2(acc2[i][3], v[6], v[7]);
        float4 r0, r1;
        r0.x = v[0] + bia0.x; r0.y = v[1] + bia0.y;
        r0.z = v[2] + bia0.z; r0.w = v[3] + bia0.w;
        r1.x = v[4] + bia1.x; r1.y = v[5] + bia1.y;
        r1.z = v[6] + bia1.z; r1.w = v[7] + bia1.w;
        if (ADD_C) {
            float4 c0 = *reinterpret_cast<const float4*>(crow);
            float4 c1 = *reinterpret_cast<const float4*>(crow + 4);
            r0.x += c0.x; r0.y += c0.y; r0.z += c0.z; r0.w += c0.w;
            r1.x += c1.x; r1.y += c1.y; r1.z += c1.z; r1.w += c1.w;
        }
        *reinterpret_cast<float4*>(crow)     = r0;
        *reinterpret_cast<float4*>(crow + 4) = r1;
        if (BF16OUT) {
            float rv[8] = {r0.x, r0.y, r0.z, r0.w, r1.x, r1.y, r1.z, r1.w};
            __nv_bfloat16 hh[8], hl[8];
#pragma unroll
            for (int m = 0; m < 8; m++) {
                hh[m] = __float2bfloat16(rv[m]);
                hl[m] = __float2bfloat16(rv[m] - __bfloat162float(hh[m]));
            }
            *reinterpret_cast<uint4*>(g_Hh + roff) = *reinterpret_cast<uint4*>(hh);
            *reinterpret_cast<uint4*>(g_Hl + roff) = *reinterpret_cast<uint4*>(hl);
        }
    }
}

// ---------------- bf16-split HMMA GEMM v2 ----------------
__global__ __launch_bounds__(256, 2) void musc_mma2() {
    extern __shared__ char smc[];
    const uint32_t smbase = (uint32_t)__cvta_generic_to_shared(smc);

    const int t = threadIdx.x;
    const int w = t >> 5;
    const int l = t & 31;
    const int wm = w & 3;
    const int wn = w >> 2;
    const int bn = blockIdx.x * 128;
    const int bm = blockIdx.y * 128;

    const int tile = t >> 6;
    const int sub  = t & 63;
    const __nv_bfloat16* gsrc =
        (tile == 0) ? g_Hh : (tile == 1) ? g_Hl : (tile == 2) ? g_WBTh : g_WBTl;
    const int gbase = (tile < 2) ? bm : bn;

    auto issue = [&](int k0, int p) {
        uint32_t dbase = smbase + (uint32_t)(p * 40960 + tile * 10240);
#pragma unroll
        for (int rr = 0; rr < 2; rr++) {
            int row = sub * 2 + rr;
            const __nv_bfloat16* s = gsrc + (size_t)(gbase + row) * HH + k0;
            uint32_t dst = dbase + (uint32_t)(row * 80);
            cp_async16(dst,      s);
            cp_async16(dst + 16, reinterpret_cast<const char*>(s) + 16);
            cp_async16(dst + 32, reinterpret_cast<const char*>(s) + 32);
            cp_async16(dst + 48, reinterpret_cast<const char*>(s) + 48);
        }
    };

    const uint32_t a_off0 = (uint32_t)((wm * 32 +      (l & 15)) * 80 + ((l >> 4) << 4));
    const uint32_t a_off1 = (uint32_t)((wm * 32 + 16 + (l & 15)) * 80 + ((l >> 4) << 4));
    const uint32_t b_row  = (uint32_t)((l & 7) + ((l >> 4) & 1) * 8);
    const uint32_t b_koff = (uint32_t)(((l >> 3) & 1) << 4);

    float acc[2][8][4];
#pragma unroll
    for (int f = 0; f < 2; f++)
#pragma unroll
        for (int i = 0; i < 8; i++)
#pragma unroll
            for (int j = 0; j < 4; j++) acc[f][i][j] = 0.0f;

    issue(0, 0);
    cp_commit();

    const int T = HH / 32;
    int p = 0;
#pragma unroll 1
    for (int tk = 0; tk < T; tk++) {
        if (tk + 1 < T) {
            issue((tk + 1) * 32, p ^ 1);
            cp_commit();
            cp_wait1();
        } else {
            cp_wait0();
        }
        __syncthreads();

        uint32_t base = smbase + (uint32_t)(p * 40960);
#pragma unroll
        for (int ks = 0; ks < 2; ks++) {
            uint32_t ksb = (uint32_t)(ks * 32);
            uint32_t ah[2][4], al[2][4];
            ldsm4(ah[0], base + a_off0 + ksb);
            ldsm4(ah[1], base + a_off1 + ksb);
            ldsm4(al[0], base + 10240 + a_off0 + ksb);
            ldsm4(al[1], base + 10240 + a_off1 + ksb);
#pragma unroll
            for (int q = 0; q < 4; q++) {
                uint32_t boff = (uint32_t)((wn * 64 + q * 16 + b_row) * 80) + b_koff + ksb;
                uint32_t bh[4], bl[4];
                ldsm4(bh, base + 20480 + boff);
                ldsm4(bl, base + 30720 + boff);
#pragma unroll
                for (int f = 0; f < 2; f++) {
#pragma unroll
                    for (int h = 0; h < 2; h++) {
                        float* a = acc[f][2 * q + h];
                        mma_bf16(a, ah[f], bh[2 * h], bh[2 * h + 1]);
                        mma_bf16(a, ah[f], bl[2 * h], bl[2 * h + 1]);
                        mma_bf16(a, al[f], bh[2 * h], bh[2 * h + 1]);
                    }
                }
            }
        }
        __syncthreads();
        p ^= 1;
    }

    const int g  = l >> 2;
    const int tt = l & 3;
#pragma unroll
    for (int f = 0; f < 2; f++) {
        int m0 = bm + wm * 32 + f * 16 + g;
#pragma unroll
        for (int nb = 0; nb < 8; nb++) {
            int n = bn + wn * 64 + nb * 8 + tt * 2;
            float2 bia = *reinterpret_cast<const float2*>(g_BMS + n);
            float2 v0 = make_float2(acc[f][nb][0] + bia.x, acc[f][nb][1] + bia.y);
            float2 v1 = make_float2(acc[f][nb][2] + bia.x, acc[f][nb][3] + bia.y);
            *reinterpret_cast<float2*>(g_MS + (size_t)m0 * NMS + n)       = v0;
            *reinterpret_cast<float2*>(g_MS + (size_t)(m0 + 8) * NMS + n) = v1;
        }
    }
}

// ---------------- fused tail chunk (d in [d0, d0+DCH)) ----------------
__global__ void fused_tail(const float* __restrict__ x, const float* __restrict__ mask,
                           float* __restrict__ out,
                           uint32_t kc0, uint32_t kc1, uint32_t kn0, uint32_t kn1,
                           int d0)
{
    int tid = blockIdx.x * blockDim.x + threadIdx.x;
    if (tid >= BB * DCH) return;
    int b = tid >> 6;
    int d = d0 + (tid & (DCH - 1));
    int t = b * DD + d;

    const float* lrow = g_LG + (size_t)b * NLG + d * 10;
    const float* mrow = g_MS + (size_t)b * NMS + d * 20;
    float lg[KK], mu[KK], sc[KK];
#pragma unroll
    for (int j = 0; j < KK; j++) lg[j] = lrow[j];
#pragma unroll
    for (int j = 0; j < KK; j++) mu[j] = mrow[j];
#pragma unroll
    for (int j = 0; j < KK; j++) {
        float v = mrow[10 + j];
        sc[j] = fmaxf(v, 0.0f) + log1pf(expf(-fabsf(v))) + 0.001f;
    }
    float q  = 1.0f - mask[t];
    float xu = x[t] * q;

    float mx = lg[0];
#pragma unroll
    for (int j = 1; j < KK; j++) mx = fmaxf(mx, lg[j]);
    float se = 0.0f;
#pragma unroll
    for (int j = 0; j < KK; j++) se += expf(lg[j] - mx);
    float lse = logf(se);

    float term[KK];
    float m2v = -1e30f;
#pragma unroll
    for (int j = 0; j < KK; j++) {
        float z   = (xu - mu[j]) / sc[j];
        float cll = -0.5f * z * z - logf(sc[j]) - 0.9189385332046727f;
        term[j] = (lg[j] - mx - lse) + cll;
        m2v = fmaxf(m2v, term[j]);
    }
    float s2 = 0.0f;
#pragma unroll
    for (int j = 0; j < KK; j++) s2 += expf(term[j] - m2v);
    out[t] = (m2v + logf(s2)) * q;

    float pm = 0.0f;
#pragma unroll
    for (int j = 0; j < KK; j++) pm += (expf(lg[j] - mx) / se) * mu[j];
    out[BB * DD + SS * BB * DD + t] = pm * q;

    float E[KK];
#pragma unroll
    for (int j = 0; j < KK; j++) E[j] = __expf(-lg[j]);

    float* smp = out + BB * DD;
    const float TINY = 1.17549435e-38f;

#pragma unroll 1
    for (int s = 0; s < SS; s++) {
        uint32_t idx_e = (uint32_t)(s * BB + b) * DD + (uint32_t)d;
        uint32_t base  = idx_e * KK;
        float e[KK];
        float m1 = 3.4e38f, m2 = 3.4e38f;
        int a = 0;
#pragma unroll
        for (int j = 0; j < KK; j++) {
            uint32_t bits = tf_bits(kc0, kc1, base + j);
            float f = bits_to_unit(bits);
            float u = fmaxf(TINY, f + TINY);
            e[j] = -logf(u);
            float mm = e[j] * E[j];
            if (mm < m1) { m2 = m1; m1 = mm; a = j; }
            else if (mm < m2) { m2 = mm; }
        }
        if (!(m2 > fmaf(m1, 1e-3f, m1))) {
            float best = -1e30f;
            a = 0;
#pragma unroll
            for (int j = 0; j < KK; j++) {
                float g = -logf(e[j]);
                float v = lg[j] + g;
                if (v > best) { best = v; a = j; }
            }
        }
        float mua = 0.f, sca = 0.f;
#pragma unroll
        for (int j = 0; j < KK; j++) {
            if (a == j) { mua = mu[j]; sca = sc[j]; }
        }
        uint32_t ebits = tf_bits(kn0, kn1, idx_e);
        const float LO = -0.99999994f;
        float u = fmaxf(LO, fmaf(bits_to_unit(ebits), 2.0f, LO));
        float eps = 1.41421356237309515f * erfinv_xla(u);
        smp[(b * SS + s) * DD + d] = (mua + sca * eps) * q;
    }
}

// ---------------- launch ----------------
extern "C" void kernel_launch(void* const* d_in, const int* in_sizes, int n_in,
                              void* d_out, int out_size)
{
    const float* x     = (const float*)d_in[0];
    const float* mask  = (const float*)d_in[1];
    const float* W_in  = (const float*)d_in[2];
    const float* b_in  = (const float*)d_in[3];
    const float* W1    = (const float*)d_in[4];
    const float* b1    = (const float*)d_in[5];
    const float* W2    = (const float*)d_in[6];
    const float* b2    = (const float*)d_in[7];
    const float* W_fin = (const float*)d_in[8];
    const float* b_fin = (const float*)d_in[9];
    float* out = (float*)d_out;

    float *dH, *dT, *dWLG, *dBLG, *dLG;
    cudaGetSymbolAddress((void**)&dH,   g_H);
    cudaGetSymbolAddress((void**)&dT,   g_T);
    cudaGetSymbolAddress((void**)&dWLG, g_WLG);
    cudaGetSymbolAddress((void**)&dBLG, g_BLG);
    cudaGetSymbolAddress((void**)&dLG,  g_LG);

    uint32_t kc0, kc1, kn0, kn1;
    threefry2x32(0u, 1234u, 0u, 0u, kc0, kc1);
    threefry2x32(0u, 1234u, 0u, 1u, kn0, kn1);

    static cudaStream_t sB = nullptr, sC = nullptr;
    static cudaEvent_t evStart, evLG, evG, evH, evM, evDone;
    static cudaEvent_t evLGc[NCHUNK];
    if (!sB) {
        cudaStreamCreateWithFlags(&sB, cudaStreamNonBlocking);
        cudaStreamCreateWithFlags(&sC, cudaStreamNonBlocking);
        cudaEventCreateWithFlags(&evStart, cudaEventDisableTiming);
        cudaEventCreateWithFlags(&evLG,    cudaEventDisableTiming);
        cudaEventCreateWithFlags(&evG,     cudaEventDisableTiming);
        cudaEventCreateWithFlags(&evH,     cudaEventDisableTiming);
        cudaEventCreateWithFlags(&evM,     cudaEventDisableTiming);
        cudaEventCreateWithFlags(&evDone,  cudaEventDisableTiming);
        for (int c = 0; c < NCHUNK; c++)
            cudaEventCreateWithFlags(&evLGc[c], cudaEventDisableTiming);
        cudaFuncSetAttribute(musc_mma2,
                             cudaFuncAttributeMaxDynamicSharedMemorySize, 2 * 40960);
    }
    const int SMEM_MMA = 2 * 40960;

    cudaEventRecord(evStart, 0);
    cudaStreamWaitEvent(sB, evStart, 0);
    gather_lg<<<(HH * NLG + NLG + 255) / 256, 256, 0, sB>>>(W_fin, b_fin);
    cudaEventRecord(evLG, sB);
    gather_ms_t<<<dim3(NMS / 32, HH / 32), 256, 0, sB>>>(W_fin);
    gather_bms<<<(NMS + 255) / 256, 256, 0, sB>>>(b_fin);
    cudaEventRecord(evG, sB);

    // main stream: layer chain (last layer fuses bf16 split of h)
    dim3 blk(128);
    dim3 g1(HH / 128, BB / 64);
    sgemm_f32x2<false, false, true, false><<<g1, blk>>>(x, mask, W_in, b_in, dH, HH, 2 * DD);
    for (int l = 0; l < LL; l++) {
        sgemm_f32x2<true, false, false, false><<<g1, blk>>>(dH, nullptr, W1 + (size_t)l * HH * HH, b1 + l * HH, dT, HH, HH);
        if (l < LL - 1)
            sgemm_f32x2<true, true, false, false><<<g1, blk>>>(dT, nullptr, W2 + (size_t)l * HH * HH, b2 + l * HH, dH, HH, HH);
        else
            sgemm_f32x2<true, true, false, true><<<g1, blk>>>(dT, nullptr, W2 + (size_t)l * HH * HH, b2 + l * HH, dH, HH, HH);
    }
    cudaEventRecord(evH, 0);

    // stream sC: means/scales HMMA (must finish before first tail chunk)
    cudaStreamWaitEvent(sC, evH, 0);
    cudaStreamWaitEvent(sC, evG, 0);
    dim3 g3(NMS / 128, BB / 128);
    musc_mma2<<<g3, 256, SMEM_MMA, sC>>>();

    // main stream: logits GEMM in NCHUNK column chunks; tail chunks pipelined on sC
    cudaStreamWaitEvent(0, evLG, 0);
    const int NCOLS = NLG / NCHUNK;             // 640 cols per chunk
    dim3 g2(NCOLS / 128, BB / 64);              // 5 x 64
    for (int c = 0; c < NCHUNK; c++) {
        int off = c * NCOLS;
        sgemm_f32x2<false, false, false, false><<<g2, blk>>>(
            dH, nullptr, dWLG + off, dBLG + off, dLG + off, NLG, HH);
        cudaEventRecord(evLGc[c], 0);
        cudaStreamWaitEvent(sC, evLGc[c], 0);
        fused_tail<<<(BB * DCH + 255) / 256, 256, 0, sC>>>(
            x, mask, out, kc0, kc1, kn0, kn1, c * DCH);
    }

    // rejoin: stream 0 waits for last tail chunk
    cudaEventRecord(evDone, sC);
    cudaStreamWaitEvent(0, evDone, 0);
}